// round 3
// baseline (speedup 1.0000x reference)
#include <cuda_runtime.h>

// Problem constants: B=128, C=3, H=W=256, PROB=0.9, BRI=CON=SAT=0.2, CUT=0.25 -> CH=CW=64.
#define B_   128
#define C_   3
#define H_   256
#define W_   256
#define CH_  64
#define CW_  64
#define PROB_ 0.9f

static constexpr int PLANE   = H_ * W_;       // 65536
static constexpr int PLANE4  = PLANE / 4;     // 16384
static constexpr int QUART4  = PLANE4 / 4;    // 4096
static constexpr int NMEAN   = B_ * C_ * 4;   // 1536 mean CTAs
static constexpr int NAUG    = B_ * (H_ / 4); // 8192 aug CTAs

__device__ float g_part[NMEAN];   // 4 partial sums per (b,c) plane
__device__ int   g_ready[B_];     // per-batch completion counter (target: 12)

// Zero the ready counters each replay (graph-capturable, trivial cost).
__global__ void init_kernel() {
    if (threadIdx.x < B_) g_ready[threadIdx.x] = 0;
}

// ---------------------------------------------------------------------------
// Fused kernel. Blocks [0,1536): quarter-plane partial sums (producers).
// Blocks [1536, 9728): augmentation (consumers), batches in REVERSE order so
// the earliest aug reads hit the freshest L2 lines from the mean phase.
// ---------------------------------------------------------------------------
__global__ __launch_bounds__(256) void fused_kernel(
    const float* __restrict__ img,
    const float* __restrict__ apply_u,
    const float* __restrict__ flip_u,
    const float* __restrict__ bri_u,
    const float* __restrict__ con_u,
    const float* __restrict__ sat_u,
    const int*   __restrict__ top_idx,
    const int*   __restrict__ left_idx,
    float* __restrict__ out)
{
    const int tid = threadIdx.x;

    if (blockIdx.x < NMEAN) {
        // ---------------- producer: partial sum of one quarter-plane ----------
        __shared__ float sm[8];
        const int q = blockIdx.x;
        const float4* p = reinterpret_cast<const float4*>(img) + (size_t)q * QUART4;

        float acc = 0.0f;
#pragma unroll
        for (int i = 0; i < 16; i++) {
            float4 v = __ldg(p + tid + i * 256);
            acc += (v.x + v.y) + (v.z + v.w);
        }
#pragma unroll
        for (int o = 16; o > 0; o >>= 1)
            acc += __shfl_xor_sync(0xFFFFFFFFu, acc, o);
        if ((tid & 31) == 0) sm[tid >> 5] = acc;
        __syncthreads();
        if (tid < 8) {
            float v = sm[tid];
#pragma unroll
            for (int o = 4; o > 0; o >>= 1)
                v += __shfl_xor_sync(0xFFu, v, o);
            if (tid == 0) {
                g_part[q] = v;
                __threadfence();
                atomicAdd(&g_ready[q / 12], 1);
            }
        }
        return;
    }

    // ---------------- consumer: augment 4 rows of one batch -------------------
    const int idx = blockIdx.x - NMEAN;
    const int b   = (B_ - 1) - (idx >> 6);        // reverse batch order
    const int h   = (idx & 63) * 4 + (tid >> 6);  // row
    const int wg  = tid & 63;                     // float4 column group
    const int w0  = wg << 2;

    // Wait for this batch's 12 partial sums.
    if (tid == 0) {
        volatile int* r = g_ready + b;
        while (*r < 12) __nanosleep(64);
    }
    __syncthreads();

    const size_t rowbase = (size_t)b * (3 * PLANE) + (size_t)h * W_;
    const float4* inR = reinterpret_cast<const float4*>(img + rowbase);
    const float4* inG = reinterpret_cast<const float4*>(img + rowbase + PLANE);
    const float4* inB = reinterpret_cast<const float4*>(img + rowbase + 2 * PLANE);
    float4* outR = reinterpret_cast<float4*>(out + rowbase);
    float4* outG = reinterpret_cast<float4*>(out + rowbase + PLANE);
    float4* outB = reinterpret_cast<float4*>(out + rowbase + 2 * PLANE);

    const bool apply = (__ldg(apply_u + b) < PROB_);
    if (!apply) {
        outR[wg] = __ldg(inR + wg);
        outG[wg] = __ldg(inG + wg);
        outB[wg] = __ldg(inB + wg);
        return;
    }

    const bool flip = (__ldg(flip_u + b) < 0.5f);
    const int  sw   = flip ? (W_ / 4 - 1 - wg) : wg;

    float4 r = __ldg(inR + sw);
    float4 g = __ldg(inG + sw);
    float4 c = __ldg(inB + sw);
    if (flip) {
        float t;
        t = r.x; r.x = r.w; r.w = t;  t = r.y; r.y = r.z; r.z = t;
        t = g.x; g.x = g.w; g.w = t;  t = g.y; g.y = g.z; g.z = t;
        t = c.x; c.x = c.w; c.w = t;  t = c.y; c.y = c.z; c.z = t;
    }

    const float bv = 0.8f + 0.4f * __ldg(bri_u + b);
    const float cv = 0.8f + 0.4f * __ldg(con_u + b);
    const float sv = 0.8f + 0.4f * __ldg(sat_u + b);

    // Fold partial sums (L2 reads — producer wrote through threadfence).
    const int pb = b * 12;
    const float inv = (1.0f / (float)PLANE);
    const float M0 = (__ldcg(g_part + pb + 0) + __ldcg(g_part + pb + 1) +
                      __ldcg(g_part + pb + 2) + __ldcg(g_part + pb + 3)) * inv * bv;
    const float M1 = (__ldcg(g_part + pb + 4) + __ldcg(g_part + pb + 5) +
                      __ldcg(g_part + pb + 6) + __ldcg(g_part + pb + 7)) * inv * bv;
    const float M2 = (__ldcg(g_part + pb + 8) + __ldcg(g_part + pb + 9) +
                      __ldcg(g_part + pb + 10) + __ldcg(g_part + pb + 11)) * inv * bv;
    const float Mbar = (M0 + M1 + M2) * (1.0f / 3.0f);

    const float A  = sv * bv * cv;
    const float D  = (1.0f - sv) * bv * cv;
    const float k  = 1.0f - cv;
    const float os = 1.0f - sv;
    const float E0 = k * (sv * M0 + os * Mbar);
    const float E1 = k * (sv * M1 + os * Mbar);
    const float E2 = k * (sv * M2 + os * Mbar);

    const int t_ = __ldg(top_idx + b);
    const int l_ = __ldg(left_idx + b);
    const bool row_in = (h >= t_) && (h < t_ + CH_);

    float4 oR, oG, oB;
    {
        float gray; bool cut; int col;

        col = w0 + 0; cut = row_in && (col >= l_) && (col < l_ + CW_);
        gray = (r.x + g.x + c.x) * (1.0f / 3.0f);
        oR.x = cut ? 0.0f : fmaf(A, r.x, fmaf(D, gray, E0));
        oG.x = cut ? 0.0f : fmaf(A, g.x, fmaf(D, gray, E1));
        oB.x = cut ? 0.0f : fmaf(A, c.x, fmaf(D, gray, E2));

        col = w0 + 1; cut = row_in && (col >= l_) && (col < l_ + CW_);
        gray = (r.y + g.y + c.y) * (1.0f / 3.0f);
        oR.y = cut ? 0.0f : fmaf(A, r.y, fmaf(D, gray, E0));
        oG.y = cut ? 0.0f : fmaf(A, g.y, fmaf(D, gray, E1));
        oB.y = cut ? 0.0f : fmaf(A, c.y, fmaf(D, gray, E2));

        col = w0 + 2; cut = row_in && (col >= l_) && (col < l_ + CW_);
        gray = (r.z + g.z + c.z) * (1.0f / 3.0f);
        oR.z = cut ? 0.0f : fmaf(A, r.z, fmaf(D, gray, E0));
        oG.z = cut ? 0.0f : fmaf(A, g.z, fmaf(D, gray, E1));
        oB.z = cut ? 0.0f : fmaf(A, c.z, fmaf(D, gray, E2));

        col = w0 + 3; cut = row_in && (col >= l_) && (col < l_ + CW_);
        gray = (r.w + g.w + c.w) * (1.0f / 3.0f);
        oR.w = cut ? 0.0f : fmaf(A, r.w, fmaf(D, gray, E0));
        oG.w = cut ? 0.0f : fmaf(A, g.w, fmaf(D, gray, E1));
        oB.w = cut ? 0.0f : fmaf(A, c.w, fmaf(D, gray, E2));
    }

    outR[wg] = oR;
    outG[wg] = oG;
    outB[wg] = oB;
}

extern "C" void kernel_launch(void* const* d_in, const int* in_sizes, int n_in,
                              void* d_out, int out_size) {
    const float* images       = (const float*)d_in[0];
    const float* apply_u      = (const float*)d_in[1];
    const float* flip_u       = (const float*)d_in[2];
    const float* brightness_u = (const float*)d_in[3];
    const float* contrast_u   = (const float*)d_in[4];
    const float* saturation_u = (const float*)d_in[5];
    const int*   top_idx      = (const int*)d_in[6];
    const int*   left_idx     = (const int*)d_in[7];
    float* out = (float*)d_out;

    init_kernel<<<1, 128>>>();
    fused_kernel<<<NMEAN + NAUG, 256>>>(images, apply_u, flip_u, brightness_u,
                                        contrast_u, saturation_u, top_idx,
                                        left_idx, out);
}

// round 4
// speedup vs baseline: 2.4556x; 2.4556x over previous
#include <cuda_runtime.h>

// Problem constants: B=128, C=3, H=W=256, PROB=0.9, BRI=CON=SAT=0.2, CUT=0.25 -> CH=CW=64.
#define B_   128
#define C_   3
#define H_   256
#define W_   256
#define CH_  64
#define CW_  64
#define PROB_ 0.9f

static constexpr int PLANE  = H_ * W_;    // 65536 floats
static constexpr int PLANE4 = PLANE / 4;  // 16384 float4
static constexpr int NT     = 1024;       // threads per block
static constexpr int IT     = PLANE4 / NT; // 16 float4 per thread per plane

// ---------------------------------------------------------------------------
// One block = one batch. Phase 1: per-channel plane sums (DRAM read).
// Phase 2: re-read (L2-hot, 0.79MB/batch), apply fused affine transform, write.
//
// Algebra (verified R1): out_ch = A*x0_ch + D*g0 + E_ch with
//   A = s*b*c ; D = (1-s)*b*c ; g0 = mean_ch(x0 pixel)
//   E_ch = (1-c)*(s*M_ch + (1-s)*Mbar),  M_ch = b*mean(raw plane ch)
// flip preserves plane means; cutout and apply are selects.
// ---------------------------------------------------------------------------
__global__ __launch_bounds__(NT) void batch_kernel(
    const float* __restrict__ img,
    const float* __restrict__ apply_u,
    const float* __restrict__ flip_u,
    const float* __restrict__ bri_u,
    const float* __restrict__ con_u,
    const float* __restrict__ sat_u,
    const int*   __restrict__ top_idx,
    const int*   __restrict__ left_idx,
    float* __restrict__ out)
{
    const int b   = blockIdx.x;
    const int tid = threadIdx.x;

    const float4* p0 = reinterpret_cast<const float4*>(img + (size_t)b * 3 * PLANE);
    const float4* p1 = p0 + PLANE4;
    const float4* p2 = p0 + 2 * PLANE4;
    float4* o0 = reinterpret_cast<float4*>(out + (size_t)b * 3 * PLANE);
    float4* o1 = o0 + PLANE4;
    float4* o2 = o0 + 2 * PLANE4;

    const bool apply = (__ldg(apply_u + b) < PROB_);

    if (!apply) {
        // Single-pass vectorized copy (uniform per block).
#pragma unroll
        for (int i = 0; i < IT; i++) {
            const int idx = tid + i * NT;
            o0[idx] = __ldg(p0 + idx);
            o1[idx] = __ldg(p1 + idx);
            o2[idx] = __ldg(p2 + idx);
        }
        return;
    }

    // ---------------- Phase 1: channel plane sums --------------------------
    float s0 = 0.0f, s1 = 0.0f, s2 = 0.0f;
#pragma unroll
    for (int i = 0; i < IT; i++) {
        const int idx = tid + i * NT;
        float4 a = __ldg(p0 + idx);
        float4 d = __ldg(p1 + idx);
        float4 e = __ldg(p2 + idx);
        s0 += (a.x + a.y) + (a.z + a.w);
        s1 += (d.x + d.y) + (d.z + d.w);
        s2 += (e.x + e.y) + (e.z + e.w);
    }
#pragma unroll
    for (int o = 16; o > 0; o >>= 1) {
        s0 += __shfl_xor_sync(0xFFFFFFFFu, s0, o);
        s1 += __shfl_xor_sync(0xFFFFFFFFu, s1, o);
        s2 += __shfl_xor_sync(0xFFFFFFFFu, s2, o);
    }

    __shared__ float smA[32], smB[32], smC[32];
    __shared__ float smMean[3];
    const int wid = tid >> 5;
    if ((tid & 31) == 0) { smA[wid] = s0; smB[wid] = s1; smC[wid] = s2; }
    __syncthreads();
    if (tid < 32) {
        float a = smA[tid], d = smB[tid], e = smC[tid];
#pragma unroll
        for (int o = 16; o > 0; o >>= 1) {
            a += __shfl_xor_sync(0xFFFFFFFFu, a, o);
            d += __shfl_xor_sync(0xFFFFFFFFu, d, o);
            e += __shfl_xor_sync(0xFFFFFFFFu, e, o);
        }
        if (tid == 0) {
            const float inv = 1.0f / (float)PLANE;
            smMean[0] = a * inv; smMean[1] = d * inv; smMean[2] = e * inv;
        }
    }
    __syncthreads();

    // ---------------- Per-batch constants -----------------------------------
    const float bv = 0.8f + 0.4f * __ldg(bri_u + b);
    const float cv = 0.8f + 0.4f * __ldg(con_u + b);
    const float sv = 0.8f + 0.4f * __ldg(sat_u + b);

    const float M0 = smMean[0] * bv;
    const float M1 = smMean[1] * bv;
    const float M2 = smMean[2] * bv;
    const float Mbar = (M0 + M1 + M2) * (1.0f / 3.0f);

    const float A  = sv * bv * cv;
    const float D  = (1.0f - sv) * bv * cv;
    const float k  = 1.0f - cv;
    const float os = 1.0f - sv;
    const float E0 = k * (sv * M0 + os * Mbar);
    const float E1 = k * (sv * M1 + os * Mbar);
    const float E2 = k * (sv * M2 + os * Mbar);

    const bool flip = (__ldg(flip_u + b) < 0.5f);
    const int  t_   = __ldg(top_idx + b);
    const int  l_   = __ldg(left_idx + b);

    // ---------------- Phase 2: transform (reads are L2-hot) ----------------
#pragma unroll
    for (int i = 0; i < IT; i++) {
        const int idx = tid + i * NT;      // output float4 index in plane
        const int h   = idx >> 6;          // row
        const int wg  = idx & 63;          // output float4 column group
        const int sw  = flip ? (63 - wg) : wg;
        const int sidx = (h << 6) + sw;

        float4 r = __ldg(p0 + sidx);
        float4 g = __ldg(p1 + sidx);
        float4 c = __ldg(p2 + sidx);
        if (flip) {
            float t;
            t = r.x; r.x = r.w; r.w = t;  t = r.y; r.y = r.z; r.z = t;
            t = g.x; g.x = g.w; g.w = t;  t = g.y; g.y = g.z; g.z = t;
            t = c.x; c.x = c.w; c.w = t;  t = c.y; c.y = c.z; c.z = t;
        }

        const bool row_in = (h >= t_) && (h < t_ + CH_);
        const int  w0 = wg << 2;

        float4 oR, oG, oB;
        float gray; bool cut; int col;

        col = w0 + 0; cut = row_in && (col >= l_) && (col < l_ + CW_);
        gray = (r.x + g.x + c.x) * (1.0f / 3.0f);
        oR.x = cut ? 0.0f : fmaf(A, r.x, fmaf(D, gray, E0));
        oG.x = cut ? 0.0f : fmaf(A, g.x, fmaf(D, gray, E1));
        oB.x = cut ? 0.0f : fmaf(A, c.x, fmaf(D, gray, E2));

        col = w0 + 1; cut = row_in && (col >= l_) && (col < l_ + CW_);
        gray = (r.y + g.y + c.y) * (1.0f / 3.0f);
        oR.y = cut ? 0.0f : fmaf(A, r.y, fmaf(D, gray, E0));
        oG.y = cut ? 0.0f : fmaf(A, g.y, fmaf(D, gray, E1));
        oB.y = cut ? 0.0f : fmaf(A, c.y, fmaf(D, gray, E2));

        col = w0 + 2; cut = row_in && (col >= l_) && (col < l_ + CW_);
        gray = (r.z + g.z + c.z) * (1.0f / 3.0f);
        oR.z = cut ? 0.0f : fmaf(A, r.z, fmaf(D, gray, E0));
        oG.z = cut ? 0.0f : fmaf(A, g.z, fmaf(D, gray, E1));
        oB.z = cut ? 0.0f : fmaf(A, c.z, fmaf(D, gray, E2));

        col = w0 + 3; cut = row_in && (col >= l_) && (col < l_ + CW_);
        gray = (r.w + g.w + c.w) * (1.0f / 3.0f);
        oR.w = cut ? 0.0f : fmaf(A, r.w, fmaf(D, gray, E0));
        oG.w = cut ? 0.0f : fmaf(A, g.w, fmaf(D, gray, E1));
        oB.w = cut ? 0.0f : fmaf(A, c.w, fmaf(D, gray, E2));

        o0[idx] = oR;
        o1[idx] = oG;
        o2[idx] = oB;
    }
}

extern "C" void kernel_launch(void* const* d_in, const int* in_sizes, int n_in,
                              void* d_out, int out_size) {
    const float* images       = (const float*)d_in[0];
    const float* apply_u      = (const float*)d_in[1];
    const float* flip_u       = (const float*)d_in[2];
    const float* brightness_u = (const float*)d_in[3];
    const float* contrast_u   = (const float*)d_in[4];
    const float* saturation_u = (const float*)d_in[5];
    const int*   top_idx      = (const int*)d_in[6];
    const int*   left_idx     = (const int*)d_in[7];
    float* out = (float*)d_out;

    batch_kernel<<<B_, NT>>>(images, apply_u, flip_u, brightness_u,
                             contrast_u, saturation_u, top_idx, left_idx, out);
}

// round 5
// speedup vs baseline: 2.5897x; 1.0546x over previous
#include <cuda_runtime.h>

// Problem constants: B=128, C=3, H=W=256, PROB=0.9, BRI=CON=SAT=0.2, CUT=0.25 -> CH=CW=64.
#define B_   128
#define C_   3
#define H_   256
#define W_   256
#define CH_  64
#define CW_  64
#define PROB_ 0.9f

static constexpr int PLANE  = H_ * W_;     // 65536 floats
static constexpr int PLANE4 = PLANE / 4;   // 16384 float4
static constexpr int NT     = 1024;        // threads per block
static constexpr int IT     = PLANE4 / NT; // 16 float4 per thread per plane

// ---------------------------------------------------------------------------
// One block = one batch. Phase 1: per-channel plane sums (DRAM read, normal
// policy so lines persist in L2). Phase 2: re-read NEWEST-FIRST with __ldcs
// (last-use: dead lines free L2 immediately), transform, store with __stcs
// (output never re-read; don't evict the input window).
//
// Algebra: out_ch = A*x0_ch + D*g0 + E_ch with
//   A = s*b*c ; D = (1-s)*b*c ; g0 = mean_ch(x0 pixel)
//   E_ch = (1-c)*(s*M_ch + (1-s)*Mbar),  M_ch = b*mean(raw plane ch)
// flip preserves plane means; cutout and apply are selects.
// ---------------------------------------------------------------------------
__global__ __launch_bounds__(NT) void batch_kernel(
    const float* __restrict__ img,
    const float* __restrict__ apply_u,
    const float* __restrict__ flip_u,
    const float* __restrict__ bri_u,
    const float* __restrict__ con_u,
    const float* __restrict__ sat_u,
    const int*   __restrict__ top_idx,
    const int*   __restrict__ left_idx,
    float* __restrict__ out)
{
    const int b   = blockIdx.x;
    const int tid = threadIdx.x;

    const float4* p0 = reinterpret_cast<const float4*>(img + (size_t)b * 3 * PLANE);
    const float4* p1 = p0 + PLANE4;
    const float4* p2 = p0 + 2 * PLANE4;
    float4* o0 = reinterpret_cast<float4*>(out + (size_t)b * 3 * PLANE);
    float4* o1 = o0 + PLANE4;
    float4* o2 = o0 + 2 * PLANE4;

    const bool apply = (__ldg(apply_u + b) < PROB_);

    if (!apply) {
        // Single-pass streaming copy (uniform per block): no reuse anywhere.
#pragma unroll
        for (int i = 0; i < IT; i++) {
            const int idx = tid + i * NT;
            __stcs(o0 + idx, __ldcs(p0 + idx));
            __stcs(o1 + idx, __ldcs(p1 + idx));
            __stcs(o2 + idx, __ldcs(p2 + idx));
        }
        return;
    }

    // ---------------- Phase 1: channel plane sums (keep lines in L2) -------
    float s0 = 0.0f, s1 = 0.0f, s2 = 0.0f;
#pragma unroll
    for (int i = 0; i < IT; i++) {
        const int idx = tid + i * NT;
        float4 a = __ldg(p0 + idx);
        float4 d = __ldg(p1 + idx);
        float4 e = __ldg(p2 + idx);
        s0 += (a.x + a.y) + (a.z + a.w);
        s1 += (d.x + d.y) + (d.z + d.w);
        s2 += (e.x + e.y) + (e.z + e.w);
    }
#pragma unroll
    for (int o = 16; o > 0; o >>= 1) {
        s0 += __shfl_xor_sync(0xFFFFFFFFu, s0, o);
        s1 += __shfl_xor_sync(0xFFFFFFFFu, s1, o);
        s2 += __shfl_xor_sync(0xFFFFFFFFu, s2, o);
    }

    __shared__ float smA[32], smB[32], smC[32];
    __shared__ float smMean[3];
    const int wid = tid >> 5;
    if ((tid & 31) == 0) { smA[wid] = s0; smB[wid] = s1; smC[wid] = s2; }
    __syncthreads();
    if (tid < 32) {
        float a = smA[tid], d = smB[tid], e = smC[tid];
#pragma unroll
        for (int o = 16; o > 0; o >>= 1) {
            a += __shfl_xor_sync(0xFFFFFFFFu, a, o);
            d += __shfl_xor_sync(0xFFFFFFFFu, d, o);
            e += __shfl_xor_sync(0xFFFFFFFFu, e, o);
        }
        if (tid == 0) {
            const float inv = 1.0f / (float)PLANE;
            smMean[0] = a * inv; smMean[1] = d * inv; smMean[2] = e * inv;
        }
    }
    __syncthreads();

    // ---------------- Per-batch constants -----------------------------------
    const float bv = 0.8f + 0.4f * __ldg(bri_u + b);
    const float cv = 0.8f + 0.4f * __ldg(con_u + b);
    const float sv = 0.8f + 0.4f * __ldg(sat_u + b);

    const float M0 = smMean[0] * bv;
    const float M1 = smMean[1] * bv;
    const float M2 = smMean[2] * bv;
    const float Mbar = (M0 + M1 + M2) * (1.0f / 3.0f);

    const float A  = sv * bv * cv;
    const float D  = (1.0f - sv) * bv * cv;
    const float k  = 1.0f - cv;
    const float os = 1.0f - sv;
    const float E0 = k * (sv * M0 + os * Mbar);
    const float E1 = k * (sv * M1 + os * Mbar);
    const float E2 = k * (sv * M2 + os * Mbar);

    const bool flip = (__ldg(flip_u + b) < 0.5f);
    const int  t_   = __ldg(top_idx + b);
    const int  l_   = __ldg(left_idx + b);

    // ---------------- Phase 2: transform, NEWEST-FIRST, last-use loads -----
#pragma unroll
    for (int i = IT - 1; i >= 0; i--) {
        const int idx = tid + i * NT;      // output float4 index in plane
        const int h   = idx >> 6;          // row
        const int wg  = idx & 63;          // output float4 column group
        const int sw  = flip ? (63 - wg) : wg;
        const int sidx = (h << 6) + sw;

        float4 r = __ldcs(p0 + sidx);
        float4 g = __ldcs(p1 + sidx);
        float4 c = __ldcs(p2 + sidx);
        if (flip) {
            float t;
            t = r.x; r.x = r.w; r.w = t;  t = r.y; r.y = r.z; r.z = t;
            t = g.x; g.x = g.w; g.w = t;  t = g.y; g.y = g.z; g.z = t;
            t = c.x; c.x = c.w; c.w = t;  t = c.y; c.y = c.z; c.z = t;
        }

        const bool row_in = (h >= t_) && (h < t_ + CH_);
        const int  w0 = wg << 2;

        float4 oR, oG, oB;
        float gray; bool cut; int col;

        col = w0 + 0; cut = row_in && (col >= l_) && (col < l_ + CW_);
        gray = (r.x + g.x + c.x) * (1.0f / 3.0f);
        oR.x = cut ? 0.0f : fmaf(A, r.x, fmaf(D, gray, E0));
        oG.x = cut ? 0.0f : fmaf(A, g.x, fmaf(D, gray, E1));
        oB.x = cut ? 0.0f : fmaf(A, c.x, fmaf(D, gray, E2));

        col = w0 + 1; cut = row_in && (col >= l_) && (col < l_ + CW_);
        gray = (r.y + g.y + c.y) * (1.0f / 3.0f);
        oR.y = cut ? 0.0f : fmaf(A, r.y, fmaf(D, gray, E0));
        oG.y = cut ? 0.0f : fmaf(A, g.y, fmaf(D, gray, E1));
        oB.y = cut ? 0.0f : fmaf(A, c.y, fmaf(D, gray, E2));

        col = w0 + 2; cut = row_in && (col >= l_) && (col < l_ + CW_);
        gray = (r.z + g.z + c.z) * (1.0f / 3.0f);
        oR.z = cut ? 0.0f : fmaf(A, r.z, fmaf(D, gray, E0));
        oG.z = cut ? 0.0f : fmaf(A, g.z, fmaf(D, gray, E1));
        oB.z = cut ? 0.0f : fmaf(A, c.z, fmaf(D, gray, E2));

        col = w0 + 3; cut = row_in && (col >= l_) && (col < l_ + CW_);
        gray = (r.w + g.w + c.w) * (1.0f / 3.0f);
        oR.w = cut ? 0.0f : fmaf(A, r.w, fmaf(D, gray, E0));
        oG.w = cut ? 0.0f : fmaf(A, g.w, fmaf(D, gray, E1));
        oB.w = cut ? 0.0f : fmaf(A, c.w, fmaf(D, gray, E2));

        __stcs(o0 + idx, oR);
        __stcs(o1 + idx, oG);
        __stcs(o2 + idx, oB);
    }
}

extern "C" void kernel_launch(void* const* d_in, const int* in_sizes, int n_in,
                              void* d_out, int out_size) {
    const float* images       = (const float*)d_in[0];
    const float* apply_u      = (const float*)d_in[1];
    const float* flip_u       = (const float*)d_in[2];
    const float* brightness_u = (const float*)d_in[3];
    const float* contrast_u   = (const float*)d_in[4];
    const float* saturation_u = (const float*)d_in[5];
    const int*   top_idx      = (const int*)d_in[6];
    const int*   left_idx     = (const int*)d_in[7];
    float* out = (float*)d_out;

    batch_kernel<<<B_, NT>>>(images, apply_u, flip_u, brightness_u,
                             contrast_u, saturation_u, top_idx, left_idx, out);
}